// round 1
// baseline (speedup 1.0000x reference)
#include <cuda_runtime.h>
#include <cstdint>

#define N_NODES 100000
#define N_EDGES 600000
#define CH 128
#define NPB 32   // nodes per block in the CH-layer kernel (N_NODES % 32 == 0)

// ---------------- scratch (static device globals; no allocation) ----------------
__device__ int   g_deg[N_NODES];
__device__ float g_deginv[N_NODES];
__device__ int   g_off[N_NODES + 1];
__device__ int   g_cur[N_NODES];
__device__ int   g_col[N_EDGES];
__device__ float g_h1[(size_t)N_NODES * CH];
__device__ float g_h2[(size_t)N_NODES * CH];

// ---------------- small helpers ----------------
__device__ __forceinline__ unsigned long long pack2(float lo, float hi) {
    unsigned long long r;
    asm("mov.b64 %0, {%1, %2};" : "=l"(r) : "f"(lo), "f"(hi));
    return r;
}
__device__ __forceinline__ unsigned long long fma2(unsigned long long a,
                                                   unsigned long long w,
                                                   unsigned long long c) {
    unsigned long long d;
    asm("fma.rn.f32x2 %0, %1, %2, %3;" : "=l"(d) : "l"(a), "l"(w), "l"(c));
    return d;
}
__device__ __forceinline__ float2 unpack2(unsigned long long v) {
    float lo, hi;
    asm("mov.b64 {%0, %1}, %2;" : "=f"(lo), "=f"(hi) : "l"(v));
    return make_float2(lo, hi);
}

// ---------------- CSR build ----------------
__global__ void zero_deg_kernel() {
    int i = blockIdx.x * blockDim.x + threadIdx.x;
    if (i < N_NODES) g_deg[i] = 0;
}

__global__ void hist_kernel(const int* __restrict__ dst) {
    int i = blockIdx.x * blockDim.x + threadIdx.x;
    if (i < N_EDGES) atomicAdd(&g_deg[dst[i]], 1);
}

// single-block sequential-chunk scan (100k elems, ~98 chunks of 1024)
__global__ void scan_kernel() {
    __shared__ int s[1024];
    __shared__ int carry_s;
    int tid = threadIdx.x;
    if (tid == 0) { carry_s = 0; g_off[0] = 0; }
    __syncthreads();
    for (int base = 0; base < N_NODES; base += 1024) {
        int i = base + tid;
        int v = (i < N_NODES) ? g_deg[i] : 0;
        if (i < N_NODES) g_deginv[i] = (v > 0) ? (1.0f / (float)v) : 0.0f;
        s[tid] = v;
        __syncthreads();
        #pragma unroll
        for (int d = 1; d < 1024; d <<= 1) {
            int t = (tid >= d) ? s[tid - d] : 0;
            __syncthreads();
            s[tid] += t;
            __syncthreads();
        }
        int incl  = s[tid];
        int carry = carry_s;
        if (i < N_NODES) {
            g_off[i + 1] = carry + incl;
            g_cur[i]     = carry + incl - v;   // exclusive offset = fill cursor
        }
        __syncthreads();
        if (tid == 1023) carry_s = carry + s[1023];
        __syncthreads();
    }
}

__global__ void fill_kernel(const int* __restrict__ src, const int* __restrict__ dst) {
    int i = blockIdx.x * blockDim.x + threadIdx.x;
    if (i < N_EDGES) {
        int d   = dst[i];
        int pos = atomicAdd(&g_cur[d], 1);
        g_col[pos] = src[i];
    }
}

// ---------------- layer 1 (K = 3, tiny) ----------------
__global__ void layer1_kernel(const float* __restrict__ x,
                              const float* __restrict__ Wl,
                              const float* __restrict__ Wr,
                              const float* __restrict__ b,
                              float* __restrict__ hout) {
    __shared__ float aggx[64][4];
    __shared__ float xs[64][4];
    int tid  = threadIdx.x;
    int warp = tid >> 5, lane = tid & 31;
    int base = blockIdx.x * 64;

    for (int n = warp; n < 64; n += 4) {
        int node = base + n;
        if (node >= N_NODES) break;
        int s0 = g_off[node], e0 = g_off[node + 1];
        float a0 = 0.f, a1 = 0.f, a2 = 0.f;
        for (int idx = s0 + lane; idx < e0; idx += 32) {
            int j = g_col[idx];
            a0 += x[j * 3 + 0];
            a1 += x[j * 3 + 1];
            a2 += x[j * 3 + 2];
        }
        #pragma unroll
        for (int o = 16; o > 0; o >>= 1) {
            a0 += __shfl_xor_sync(0xffffffffu, a0, o);
            a1 += __shfl_xor_sync(0xffffffffu, a1, o);
            a2 += __shfl_xor_sync(0xffffffffu, a2, o);
        }
        if (lane == 0) {
            float di = g_deginv[node];
            aggx[n][0] = a0 * di; aggx[n][1] = a1 * di; aggx[n][2] = a2 * di;
            xs[n][0] = x[node * 3 + 0];
            xs[n][1] = x[node * 3 + 1];
            xs[n][2] = x[node * 3 + 2];
        }
    }
    __syncthreads();

    int t = tid;
    float wl0 = Wl[0 * CH + t], wl1 = Wl[1 * CH + t], wl2 = Wl[2 * CH + t];
    float wr0 = Wr[0 * CH + t], wr1 = Wr[1 * CH + t], wr2 = Wr[2 * CH + t];
    float bb  = b[t];
    for (int n = 0; n < 64; n++) {
        int node = base + n;
        if (node >= N_NODES) break;
        float acc = bb;
        acc += aggx[n][0] * wl0 + aggx[n][1] * wl1 + aggx[n][2] * wl2;
        acc += xs[n][0]   * wr0 + xs[n][1]   * wr1 + xs[n][2]   * wr2;
        hout[(size_t)node * CH + t] = fmaxf(acc, 0.0f);
    }
}

// ---------------- layers 2/3: fused gather-aggregate + dual GEMM + relu ----------------
__global__ void __launch_bounds__(128)
layerCH_kernel(const float* __restrict__ hin, float* __restrict__ hout,
               const float* __restrict__ Wl, const float* __restrict__ Wr,
               const float* __restrict__ b) {
    __shared__ __align__(16) float agg_s[NPB * CH];
    __shared__ __align__(16) float hs_s[NPB * CH];
    __shared__ __align__(16) float out_s[NPB * CH];

    int tid  = threadIdx.x;
    int warp = tid >> 5, lane = tid & 31;
    int base = blockIdx.x * NPB;   // N_NODES % NPB == 0, no guards needed

    // ---- Phase A: mean-aggregate neighbor rows + own row into shared ----
    for (int n = warp; n < NPB; n += 4) {
        int node = base + n;
        float4 own = *(const float4*)&hin[(size_t)node * CH + lane * 4];
        *(float4*)&hs_s[n * CH + lane * 4] = own;

        int s0 = g_off[node], e0 = g_off[node + 1];
        float4 A0 = make_float4(0.f, 0.f, 0.f, 0.f);
        float4 A1 = A0, A2 = A0, A3 = A0;
        int idx = s0;
        for (; idx + 4 <= e0; idx += 4) {   // MLP=4 on the gather
            int j0 = g_col[idx + 0], j1 = g_col[idx + 1];
            int j2 = g_col[idx + 2], j3 = g_col[idx + 3];
            float4 v0 = *(const float4*)&hin[(size_t)j0 * CH + lane * 4];
            float4 v1 = *(const float4*)&hin[(size_t)j1 * CH + lane * 4];
            float4 v2 = *(const float4*)&hin[(size_t)j2 * CH + lane * 4];
            float4 v3 = *(const float4*)&hin[(size_t)j3 * CH + lane * 4];
            A0.x += v0.x; A0.y += v0.y; A0.z += v0.z; A0.w += v0.w;
            A1.x += v1.x; A1.y += v1.y; A1.z += v1.z; A1.w += v1.w;
            A2.x += v2.x; A2.y += v2.y; A2.z += v2.z; A2.w += v2.w;
            A3.x += v3.x; A3.y += v3.y; A3.z += v3.z; A3.w += v3.w;
        }
        for (; idx < e0; idx++) {
            int j = g_col[idx];
            float4 v = *(const float4*)&hin[(size_t)j * CH + lane * 4];
            A0.x += v.x; A0.y += v.y; A0.z += v.z; A0.w += v.w;
        }
        float di = g_deginv[node];
        float4 A;
        A.x = ((A0.x + A1.x) + (A2.x + A3.x)) * di;
        A.y = ((A0.y + A1.y) + (A2.y + A3.y)) * di;
        A.z = ((A0.z + A1.z) + (A2.z + A3.z)) * di;
        A.w = ((A0.w + A1.w) + (A2.w + A3.w)) * di;
        *(float4*)&agg_s[n * CH + lane * 4] = A;
    }
    __syncthreads();

    // ---- Phase B: out[n][t] = b[t] + agg[n]·Wl[:,t] + h[n]·Wr[:,t], f32x2-packed ----
    int t = tid;
    float bb = b[t];
    #pragma unroll
    for (int sp = 0; sp < 4; sp++) {
        const float* W = (sp < 2) ? Wl : Wr;
        const float* S = (sp < 2) ? agg_s : hs_s;
        int kh = sp & 1;                       // k-half: [0,64) or [64,128)

        unsigned long long w2[32];             // {W[2i][t], W[2i+1][t]} pairs
        const float* wb = W + (kh * 64) * CH + t;
        #pragma unroll
        for (int i2 = 0; i2 < 32; i2++)
            w2[i2] = pack2(wb[(2 * i2) * CH], wb[(2 * i2 + 1) * CH]);

        for (int n = 0; n < NPB; n++) {
            float init = (sp == 0) ? bb : out_s[n * CH + t];
            unsigned long long acca = pack2(init, 0.0f);
            unsigned long long accb = pack2(0.0f, 0.0f);
            const ulonglong2* p = (const ulonglong2*)(S + n * CH + kh * 64);
            #pragma unroll
            for (int i4 = 0; i4 < 16; i4++) {
                ulonglong2 u = p[i4];          // 4 floats = 2 packed f32x2 pairs
                acca = fma2(u.x, w2[2 * i4 + 0], acca);
                accb = fma2(u.y, w2[2 * i4 + 1], accb);
            }
            float2 fa = unpack2(acca);
            float2 fb = unpack2(accb);
            out_s[n * CH + t] = (fa.x + fa.y) + (fb.x + fb.y);
        }
    }

    // ---- epilogue: relu + store ----
    for (int n = 0; n < NPB; n++) {
        int node = base + n;
        hout[(size_t)node * CH + t] = fmaxf(out_s[n * CH + t], 0.0f);
    }
}

// ---------------- launch ----------------
extern "C" void kernel_launch(void* const* d_in, const int* in_sizes, int n_in,
                              void* d_out, int out_size) {
    const float* x   = (const float*)d_in[0];
    const int*   ei  = (const int*)d_in[1];      // [2, E]
    const float* W1l = (const float*)d_in[2];
    const float* W1r = (const float*)d_in[3];
    const float* b1  = (const float*)d_in[4];
    const float* W2l = (const float*)d_in[5];
    const float* W2r = (const float*)d_in[6];
    const float* b2  = (const float*)d_in[7];
    const float* W3l = (const float*)d_in[8];
    const float* W3r = (const float*)d_in[9];
    const float* b3  = (const float*)d_in[10];
    float* out = (float*)d_out;

    const int* src = ei;
    const int* dst = ei + N_EDGES;

    // per-call pointers into static scratch (resolved on device side via globals)
    float* h1; float* h2;
    cudaGetSymbolAddress((void**)&h1, g_h1);
    cudaGetSymbolAddress((void**)&h2, g_h2);

    // CSR build
    zero_deg_kernel<<<(N_NODES + 255) / 256, 256>>>();
    hist_kernel<<<(N_EDGES + 255) / 256, 256>>>(dst);
    scan_kernel<<<1, 1024>>>();
    fill_kernel<<<(N_EDGES + 255) / 256, 256>>>(src, dst);

    // layers
    layer1_kernel<<<(N_NODES + 63) / 64, 128>>>(x, W1l, W1r, b1, h1);
    layerCH_kernel<<<N_NODES / NPB, 128>>>(h1, h2, W2l, W2r, b2);
    layerCH_kernel<<<N_NODES / NPB, 128>>>(h2, out, W3l, W3r, b3);
}

// round 2
// speedup vs baseline: 1.1126x; 1.1126x over previous
#include <cuda_runtime.h>
#include <cstdint>

#define N_NODES 100000
#define N_EDGES 600000
#define CH 128
#define NPB 32   // nodes per block in the CH-layer kernel (N_NODES % 32 == 0)

// ---------------- scratch (static device globals; no allocation) ----------------
__device__ int   g_deg[N_NODES];
__device__ float g_deginv[N_NODES];
__device__ int   g_off[N_NODES + 1];
__device__ int   g_cur[N_NODES];
__device__ int   g_col[N_EDGES];
__device__ float g_h1[(size_t)N_NODES * CH];
__device__ float g_h2[(size_t)N_NODES * CH];

// ---------------- small helpers ----------------
__device__ __forceinline__ unsigned long long pack2(float lo, float hi) {
    unsigned long long r;
    asm("mov.b64 %0, {%1, %2};" : "=l"(r) : "f"(lo), "f"(hi));
    return r;
}
__device__ __forceinline__ unsigned long long fma2(unsigned long long a,
                                                   unsigned long long w,
                                                   unsigned long long c) {
    unsigned long long d;
    asm("fma.rn.f32x2 %0, %1, %2, %3;" : "=l"(d) : "l"(a), "l"(w), "l"(c));
    return d;
}
__device__ __forceinline__ float2 unpack2(unsigned long long v) {
    float lo, hi;
    asm("mov.b64 {%0, %1}, %2;" : "=f"(lo), "=f"(hi) : "l"(v));
    return make_float2(lo, hi);
}
__device__ __forceinline__ int warp_incl_scan(int v, int lane) {
    #pragma unroll
    for (int o = 1; o < 32; o <<= 1) {
        int t = __shfl_up_sync(0xffffffffu, v, o);
        if (lane >= o) v += t;
    }
    return v;
}

// ---------------- CSR build ----------------
__global__ void zero_deg_kernel() {
    int i = blockIdx.x * blockDim.x + threadIdx.x;
    if (i < N_NODES) g_deg[i] = 0;
}

__global__ void hist_kernel(const int* __restrict__ dst) {
    int i = blockIdx.x * blockDim.x + threadIdx.x;
    if (i < N_EDGES) atomicAdd(&g_deg[dst[i]], 1);
}

// single-block scan, warp-shuffle based: 4 barriers per 1024-chunk
__global__ void scan_kernel() {
    __shared__ int wsum[32];
    __shared__ int tot_s;
    __shared__ int carry_s;
    int tid  = threadIdx.x;
    int wid  = tid >> 5, lane = tid & 31;
    if (tid == 0) { carry_s = 0; g_off[0] = 0; }
    __syncthreads();

    for (int base = 0; base < N_NODES; base += 1024) {
        int i = base + tid;
        int v = (i < N_NODES) ? g_deg[i] : 0;
        if (i < N_NODES) g_deginv[i] = (v > 0) ? (1.0f / (float)v) : 0.0f;

        int incl = warp_incl_scan(v, lane);
        if (lane == 31) wsum[wid] = incl;
        __syncthreads();

        if (wid == 0) {
            int ws = wsum[lane];
            int wincl = warp_incl_scan(ws, lane);
            wsum[lane] = wincl - ws;          // exclusive warp prefix
            if (lane == 31) tot_s = wincl;    // chunk total
        }
        __syncthreads();

        int inclusive = carry_s + wsum[wid] + incl;
        if (i < N_NODES) {
            g_off[i + 1] = inclusive;
            g_cur[i]     = inclusive - v;     // exclusive offset = fill cursor
        }
        __syncthreads();
        if (tid == 0) carry_s += tot_s;
        __syncthreads();
    }
}

__global__ void fill_kernel(const int* __restrict__ src, const int* __restrict__ dst) {
    int i = blockIdx.x * blockDim.x + threadIdx.x;
    if (i < N_EDGES) {
        int d   = dst[i];
        int pos = atomicAdd(&g_cur[d], 1);
        g_col[pos] = src[i];
    }
}

// ---------------- layer 1 (K = 3, tiny) ----------------
__global__ void layer1_kernel(const float* __restrict__ x,
                              const float* __restrict__ Wl,
                              const float* __restrict__ Wr,
                              const float* __restrict__ b,
                              float* __restrict__ hout) {
    __shared__ float aggx[64][4];
    __shared__ float xs[64][4];
    int tid  = threadIdx.x;
    int warp = tid >> 5, lane = tid & 31;
    int base = blockIdx.x * 64;

    for (int n = warp; n < 64; n += 4) {
        int node = base + n;
        if (node >= N_NODES) break;
        int s0 = g_off[node], e0 = g_off[node + 1];
        float a0 = 0.f, a1 = 0.f, a2 = 0.f;
        for (int idx = s0 + lane; idx < e0; idx += 32) {
            int j = g_col[idx];
            a0 += x[j * 3 + 0];
            a1 += x[j * 3 + 1];
            a2 += x[j * 3 + 2];
        }
        #pragma unroll
        for (int o = 16; o > 0; o >>= 1) {
            a0 += __shfl_xor_sync(0xffffffffu, a0, o);
            a1 += __shfl_xor_sync(0xffffffffu, a1, o);
            a2 += __shfl_xor_sync(0xffffffffu, a2, o);
        }
        if (lane == 0) {
            float di = g_deginv[node];
            aggx[n][0] = a0 * di; aggx[n][1] = a1 * di; aggx[n][2] = a2 * di;
            xs[n][0] = x[node * 3 + 0];
            xs[n][1] = x[node * 3 + 1];
            xs[n][2] = x[node * 3 + 2];
        }
    }
    __syncthreads();

    int t = tid;
    float wl0 = Wl[0 * CH + t], wl1 = Wl[1 * CH + t], wl2 = Wl[2 * CH + t];
    float wr0 = Wr[0 * CH + t], wr1 = Wr[1 * CH + t], wr2 = Wr[2 * CH + t];
    float bb  = b[t];
    for (int n = 0; n < 64; n++) {
        int node = base + n;
        if (node >= N_NODES) break;
        float acc = bb;
        acc += aggx[n][0] * wl0 + aggx[n][1] * wl1 + aggx[n][2] * wl2;
        acc += xs[n][0]   * wr0 + xs[n][1]   * wr1 + xs[n][2]   * wr2;
        hout[(size_t)node * CH + t] = fmaxf(acc, 0.0f);
    }
}

// ---------------- layers 2/3: fused gather-aggregate + dual GEMM + relu ----------------
__global__ void __launch_bounds__(128, 4)
layerCH_kernel(const float* __restrict__ hin, float* __restrict__ hout,
               const float* __restrict__ Wl, const float* __restrict__ Wr,
               const float* __restrict__ b) {
    __shared__ __align__(16) float agg_s[NPB * CH];
    __shared__ __align__(16) float hs_s[NPB * CH];
    __shared__ __align__(16) float out_s[NPB * CH];

    int tid  = threadIdx.x;
    int warp = tid >> 5, lane = tid & 31;
    int base = blockIdx.x * NPB;   // N_NODES % NPB == 0, no guards needed

    // ---- Phase A: mean-aggregate neighbor rows + own row into shared ----
    for (int n = warp; n < NPB; n += 4) {
        int node = base + n;
        float4 own = *(const float4*)&hin[(size_t)node * CH + lane * 4];
        *(float4*)&hs_s[n * CH + lane * 4] = own;

        int s0 = g_off[node], e0 = g_off[node + 1];
        float4 A0 = make_float4(0.f, 0.f, 0.f, 0.f);
        float4 A1 = A0, A2 = A0, A3 = A0;
        int idx = s0;
        for (; idx + 4 <= e0; idx += 4) {   // MLP=4 on the gather
            int j0 = g_col[idx + 0], j1 = g_col[idx + 1];
            int j2 = g_col[idx + 2], j3 = g_col[idx + 3];
            float4 v0 = *(const float4*)&hin[(size_t)j0 * CH + lane * 4];
            float4 v1 = *(const float4*)&hin[(size_t)j1 * CH + lane * 4];
            float4 v2 = *(const float4*)&hin[(size_t)j2 * CH + lane * 4];
            float4 v3 = *(const float4*)&hin[(size_t)j3 * CH + lane * 4];
            A0.x += v0.x; A0.y += v0.y; A0.z += v0.z; A0.w += v0.w;
            A1.x += v1.x; A1.y += v1.y; A1.z += v1.z; A1.w += v1.w;
            A2.x += v2.x; A2.y += v2.y; A2.z += v2.z; A2.w += v2.w;
            A3.x += v3.x; A3.y += v3.y; A3.z += v3.z; A3.w += v3.w;
        }
        for (; idx < e0; idx++) {
            int j = g_col[idx];
            float4 v = *(const float4*)&hin[(size_t)j * CH + lane * 4];
            A0.x += v.x; A0.y += v.y; A0.z += v.z; A0.w += v.w;
        }
        float di = g_deginv[node];
        float4 A;
        A.x = ((A0.x + A1.x) + (A2.x + A3.x)) * di;
        A.y = ((A0.y + A1.y) + (A2.y + A3.y)) * di;
        A.z = ((A0.z + A1.z) + (A2.z + A3.z)) * di;
        A.w = ((A0.w + A1.w) + (A2.w + A3.w)) * di;
        *(float4*)&agg_s[n * CH + lane * 4] = A;
    }
    __syncthreads();

    // ---- Phase B: out[n][t] = b[t] + agg[n]·Wl[:,t] + h[n]·Wr[:,t], f32x2-packed ----
    int t = tid;
    float bb = b[t];
    #pragma unroll
    for (int sp = 0; sp < 4; sp++) {
        const float* W = (sp < 2) ? Wl : Wr;
        const float* S = (sp < 2) ? agg_s : hs_s;
        int kh = sp & 1;                       // k-half: [0,64) or [64,128)

        unsigned long long w2[32];             // {W[2i][t], W[2i+1][t]} pairs
        const float* wb = W + (kh * 64) * CH + t;
        #pragma unroll
        for (int i2 = 0; i2 < 32; i2++)
            w2[i2] = pack2(wb[(2 * i2) * CH], wb[(2 * i2 + 1) * CH]);

        for (int n = 0; n < NPB; n++) {
            float init = (sp == 0) ? bb : out_s[n * CH + t];
            unsigned long long acc0 = pack2(init, 0.0f);
            unsigned long long acc1 = pack2(0.0f, 0.0f);
            unsigned long long acc2 = acc1;
            unsigned long long acc3 = acc1;
            const ulonglong2* p = (const ulonglong2*)(S + n * CH + kh * 64);
            #pragma unroll
            for (int i8 = 0; i8 < 8; i8++) {   // 4 independent chains, depth 8
                ulonglong2 u0 = p[2 * i8 + 0];
                ulonglong2 u1 = p[2 * i8 + 1];
                acc0 = fma2(u0.x, w2[4 * i8 + 0], acc0);
                acc1 = fma2(u0.y, w2[4 * i8 + 1], acc1);
                acc2 = fma2(u1.x, w2[4 * i8 + 2], acc2);
                acc3 = fma2(u1.y, w2[4 * i8 + 3], acc3);
            }
            float2 f0 = unpack2(acc0);
            float2 f1 = unpack2(acc1);
            float2 f2 = unpack2(acc2);
            float2 f3 = unpack2(acc3);
            out_s[n * CH + t] = ((f0.x + f0.y) + (f1.x + f1.y))
                              + ((f2.x + f2.y) + (f3.x + f3.y));
        }
    }

    // ---- epilogue: relu + store ----
    for (int n = 0; n < NPB; n++) {
        int node = base + n;
        hout[(size_t)node * CH + t] = fmaxf(out_s[n * CH + t], 0.0f);
    }
}

// ---------------- launch ----------------
extern "C" void kernel_launch(void* const* d_in, const int* in_sizes, int n_in,
                              void* d_out, int out_size) {
    const float* x   = (const float*)d_in[0];
    const int*   ei  = (const int*)d_in[1];      // [2, E]
    const float* W1l = (const float*)d_in[2];
    const float* W1r = (const float*)d_in[3];
    const float* b1  = (const float*)d_in[4];
    const float* W2l = (const float*)d_in[5];
    const float* W2r = (const float*)d_in[6];
    const float* b2  = (const float*)d_in[7];
    const float* W3l = (const float*)d_in[8];
    const float* W3r = (const float*)d_in[9];
    const float* b3  = (const float*)d_in[10];
    float* out = (float*)d_out;

    const int* src = ei;
    const int* dst = ei + N_EDGES;

    float* h1; float* h2;
    cudaGetSymbolAddress((void**)&h1, g_h1);
    cudaGetSymbolAddress((void**)&h2, g_h2);

    // CSR build
    zero_deg_kernel<<<(N_NODES + 255) / 256, 256>>>();
    hist_kernel<<<(N_EDGES + 255) / 256, 256>>>(dst);
    scan_kernel<<<1, 1024>>>();
    fill_kernel<<<(N_EDGES + 255) / 256, 256>>>(src, dst);

    // layers
    layer1_kernel<<<(N_NODES + 63) / 64, 128>>>(x, W1l, W1r, b1, h1);
    layerCH_kernel<<<N_NODES / NPB, 128>>>(h1, h2, W2l, W2r, b2);
    layerCH_kernel<<<N_NODES / NPB, 128>>>(h2, out, W3l, W3r, b3);
}

// round 4
// speedup vs baseline: 1.8261x; 1.6413x over previous
#include <cuda_runtime.h>
#include <cstdint>

#define N_NODES 100000
#define N_EDGES 600000
#define CH 128
#define NPB 32            // nodes per block tile (100000 % 32 == 0 -> 3125 blocks)
#define NCHUNK 98         // ceil(100000/1024)

// ---------------- scratch (static device globals; no allocation) ----------------
__device__ int   g_deg[N_NODES];
__device__ float g_deginv[N_NODES];
__device__ int   g_off[N_NODES + 1];
__device__ int   g_cur[N_NODES];
__device__ int   g_col[N_EDGES];
__device__ int   g_chunksum[NCHUNK];
__device__ int   g_chunkoff[NCHUNK];
__device__ float g_h1[(size_t)N_NODES * CH];
__device__ float g_h2[(size_t)N_NODES * CH];
__device__ float g_Wt2[128 * 256];   // [n][k] tf32-rounded, k<128 = W2l, k>=128 = W2r
__device__ float g_Wt3[128 * 256];

// ---------------- helpers ----------------
__device__ __forceinline__ float tf32r(float x) {
    unsigned r;
    asm("cvt.rna.tf32.f32 %0, %1;" : "=r"(r) : "f"(x));   // tf32 cvt writes .b32
    return __uint_as_float(r);
}
__device__ __forceinline__ int warp_incl_scan(int v, int lane) {
    #pragma unroll
    for (int o = 1; o < 32; o <<= 1) {
        int t = __shfl_up_sync(0xffffffffu, v, o);
        if (lane >= o) v += t;
    }
    return v;
}
__device__ __forceinline__ void mma_tf32(float* c, const unsigned* a, const unsigned* b) {
    asm volatile(
        "mma.sync.aligned.m16n8k8.row.col.f32.tf32.tf32.f32 "
        "{%0,%1,%2,%3}, {%4,%5,%6,%7}, {%8,%9}, {%0,%1,%2,%3};"
        : "+f"(c[0]), "+f"(c[1]), "+f"(c[2]), "+f"(c[3])
        : "r"(a[0]), "r"(a[1]), "r"(a[2]), "r"(a[3]), "r"(b[0]), "r"(b[1]));
}

// ---------------- weight prep: transpose + concat + tf32 round ----------------
__global__ void prep_kernel(const float* __restrict__ W2l, const float* __restrict__ W2r,
                            const float* __restrict__ W3l, const float* __restrict__ W3r) {
    int idx = blockIdx.x * blockDim.x + threadIdx.x;   // 128*256 = 32768
    if (idx >= 128 * 256) return;
    int n = idx >> 8, k = idx & 255;
    float v2 = (k < 128) ? W2l[k * CH + n] : W2r[(k - 128) * CH + n];
    float v3 = (k < 128) ? W3l[k * CH + n] : W3r[(k - 128) * CH + n];
    g_Wt2[idx] = tf32r(v2);
    g_Wt3[idx] = tf32r(v3);
}

// ---------------- CSR build ----------------
__global__ void zero_deg_kernel() {
    int i = blockIdx.x * blockDim.x + threadIdx.x;
    if (i < N_NODES) g_deg[i] = 0;
}

__global__ void hist_kernel(const int* __restrict__ dst) {
    int i = blockIdx.x * blockDim.x + threadIdx.x;
    if (i < N_EDGES) atomicAdd(&g_deg[dst[i]], 1);
}

// phase 1: per-1024-chunk inclusive scan (parallel over chunks)
__global__ void scan1_kernel() {
    __shared__ int wsum[32];
    int b = blockIdx.x, tid = threadIdx.x;
    int wid = tid >> 5, lane = tid & 31;
    int i = b * 1024 + tid;
    int v = (i < N_NODES) ? g_deg[i] : 0;
    if (i < N_NODES) g_deginv[i] = (v > 0) ? (1.0f / (float)v) : 0.0f;

    int incl = warp_incl_scan(v, lane);
    if (lane == 31) wsum[wid] = incl;
    __syncthreads();
    if (wid == 0) {
        int ws = wsum[lane];
        int wi = warp_incl_scan(ws, lane);
        wsum[lane] = wi - ws;   // exclusive warp prefix
    }
    __syncthreads();
    int inclusive = wsum[wid] + incl;
    if (i < N_NODES) g_off[i + 1] = inclusive;      // chunk-local inclusive
    if (tid == 1023) g_chunksum[b] = inclusive;     // chunk total
}

// phase 2: scan the 98 chunk sums
__global__ void scan2_kernel() {
    __shared__ int ws[4];
    int tid = threadIdx.x, wid = tid >> 5, lane = tid & 31;
    int v = (tid < NCHUNK) ? g_chunksum[tid] : 0;
    int incl = warp_incl_scan(v, lane);
    if (lane == 31) ws[wid] = incl;
    __syncthreads();
    int woff = 0;
    #pragma unroll
    for (int w = 0; w < 4; w++) if (w < wid) woff += ws[w];
    if (tid < NCHUNK) g_chunkoff[tid] = woff + incl - v;   // exclusive chunk offset
}

// phase 3: add chunk offsets back, produce g_off / g_cur
__global__ void scan3_kernel() {
    int b = blockIdx.x, tid = threadIdx.x;
    int i = b * 1024 + tid;
    if (i < N_NODES) {
        int incl = g_off[i + 1] + g_chunkoff[b];
        g_off[i + 1] = incl;
        g_cur[i]     = incl - g_deg[i];
        if (i == 0) g_off[0] = 0;
    }
}

__global__ void fill_kernel(const int* __restrict__ src, const int* __restrict__ dst) {
    int i = blockIdx.x * blockDim.x + threadIdx.x;
    if (i < N_EDGES) {
        int d   = dst[i];
        int pos = atomicAdd(&g_cur[d], 1);
        g_col[pos] = src[i];
    }
}

// ---------------- layer 1 (K = 3, exact fp32) ----------------
__global__ void layer1_kernel(const float* __restrict__ x,
                              const float* __restrict__ Wl,
                              const float* __restrict__ Wr,
                              const float* __restrict__ b,
                              float* __restrict__ hout) {
    __shared__ float aggx[64][4];
    __shared__ float xs[64][4];
    int tid  = threadIdx.x;
    int warp = tid >> 5, lane = tid & 31;
    int base = blockIdx.x * 64;

    for (int n = warp; n < 64; n += 4) {
        int node = base + n;
        if (node >= N_NODES) break;
        int s0 = g_off[node], e0 = g_off[node + 1];
        float a0 = 0.f, a1 = 0.f, a2 = 0.f;
        for (int idx = s0 + lane; idx < e0; idx += 32) {
            int j = g_col[idx];
            a0 += x[j * 3 + 0];
            a1 += x[j * 3 + 1];
            a2 += x[j * 3 + 2];
        }
        #pragma unroll
        for (int o = 16; o > 0; o >>= 1) {
            a0 += __shfl_xor_sync(0xffffffffu, a0, o);
            a1 += __shfl_xor_sync(0xffffffffu, a1, o);
            a2 += __shfl_xor_sync(0xffffffffu, a2, o);
        }
        if (lane == 0) {
            float di = g_deginv[node];
            aggx[n][0] = a0 * di; aggx[n][1] = a1 * di; aggx[n][2] = a2 * di;
            xs[n][0] = x[node * 3 + 0];
            xs[n][1] = x[node * 3 + 1];
            xs[n][2] = x[node * 3 + 2];
        }
    }
    __syncthreads();

    int t = tid;
    float wl0 = Wl[0 * CH + t], wl1 = Wl[1 * CH + t], wl2 = Wl[2 * CH + t];
    float wr0 = Wr[0 * CH + t], wr1 = Wr[1 * CH + t], wr2 = Wr[2 * CH + t];
    float bb  = b[t];
    for (int n = 0; n < 64; n++) {
        int node = base + n;
        if (node >= N_NODES) break;
        float acc = bb;
        acc += aggx[n][0] * wl0 + aggx[n][1] * wl1 + aggx[n][2] * wl2;
        acc += xs[n][0]   * wr0 + xs[n][1]   * wr1 + xs[n][2]   * wr2;
        hout[(size_t)node * CH + t] = fmaxf(acc, 0.0f);
    }
}

// ---------------- layers 2/3: gather-aggregate + tf32 tensor-core GEMM + relu ----------------
// A tile = [agg | own] : 32 nodes x 256 K, vs Wt (128 n x 256 k) -> 32x128 out.
#define AS_STRIDE 260
__global__ void __launch_bounds__(256)
layerTC_kernel(const float* __restrict__ hin, float* __restrict__ hout,
               const float* __restrict__ Wt, const float* __restrict__ bias) {
    __shared__ __align__(16) float As[NPB][AS_STRIDE];   // 33,280 B

    int tid  = threadIdx.x;
    int warp = tid >> 5, lane = tid & 31;
    int base = blockIdx.x * NPB;

    // ---- Phase A: mean-aggregate + own row, tf32-rounded, into shared ----
    for (int n = warp; n < NPB; n += 8) {
        int node = base + n;
        float4 own = *(const float4*)&hin[(size_t)node * CH + lane * 4];

        int s0 = g_off[node], e0 = g_off[node + 1];
        float4 A0 = make_float4(0.f, 0.f, 0.f, 0.f);
        float4 A1 = A0, A2 = A0, A3 = A0;
        int idx = s0;
        for (; idx + 4 <= e0; idx += 4) {
            int j0 = g_col[idx + 0], j1 = g_col[idx + 1];
            int j2 = g_col[idx + 2], j3 = g_col[idx + 3];
            float4 v0 = *(const float4*)&hin[(size_t)j0 * CH + lane * 4];
            float4 v1 = *(const float4*)&hin[(size_t)j1 * CH + lane * 4];
            float4 v2 = *(const float4*)&hin[(size_t)j2 * CH + lane * 4];
            float4 v3 = *(const float4*)&hin[(size_t)j3 * CH + lane * 4];
            A0.x += v0.x; A0.y += v0.y; A0.z += v0.z; A0.w += v0.w;
            A1.x += v1.x; A1.y += v1.y; A1.z += v1.z; A1.w += v1.w;
            A2.x += v2.x; A2.y += v2.y; A2.z += v2.z; A2.w += v2.w;
            A3.x += v3.x; A3.y += v3.y; A3.z += v3.z; A3.w += v3.w;
        }
        for (; idx < e0; idx++) {
            int j = g_col[idx];
            float4 v = *(const float4*)&hin[(size_t)j * CH + lane * 4];
            A0.x += v.x; A0.y += v.y; A0.z += v.z; A0.w += v.w;
        }
        float di = g_deginv[node];
        As[n][lane * 4 + 0] = tf32r(((A0.x + A1.x) + (A2.x + A3.x)) * di);
        As[n][lane * 4 + 1] = tf32r(((A0.y + A1.y) + (A2.y + A3.y)) * di);
        As[n][lane * 4 + 2] = tf32r(((A0.z + A1.z) + (A2.z + A3.z)) * di);
        As[n][lane * 4 + 3] = tf32r(((A0.w + A1.w) + (A2.w + A3.w)) * di);
        As[n][128 + lane * 4 + 0] = tf32r(own.x);
        As[n][128 + lane * 4 + 1] = tf32r(own.y);
        As[n][128 + lane * 4 + 2] = tf32r(own.z);
        As[n][128 + lane * 4 + 3] = tf32r(own.w);
    }
    __syncthreads();

    // ---- Phase B: 32x128 = (32x256) @ (256x128) via m16n8k8 tf32 mma ----
    // warp w covers output cols [w*16, w*16+16): 2 n-tiles; 2 m-tiles; 32 k-tiles.
    int gid = lane >> 2, tig = lane & 3;
    float acc[2][2][4];
    #pragma unroll
    for (int mt = 0; mt < 2; mt++)
        #pragma unroll
        for (int nt = 0; nt < 2; nt++)
            #pragma unroll
            for (int r = 0; r < 4; r++) acc[mt][nt][r] = 0.0f;

    const unsigned* WtU = (const unsigned*)Wt;
    const unsigned* AsU = (const unsigned*)&As[0][0];
    // per-lane base for B: row n = warp*16 + nt*8 + gid, col k = kt*8 + tig
    unsigned wrow0 = (warp * 16 + gid) * 256 + tig;        // nt=0
    unsigned wrow1 = wrow0 + 8 * 256;                      // nt=1

    #pragma unroll 4
    for (int kt = 0; kt < 32; kt++) {
        unsigned kc = kt * 8;
        unsigned b0[2], b1[2];
        b0[0] = WtU[wrow0 + kc];     b0[1] = WtU[wrow0 + kc + 4];
        b1[0] = WtU[wrow1 + kc];     b1[1] = WtU[wrow1 + kc + 4];

        #pragma unroll
        for (int mt = 0; mt < 2; mt++) {
            unsigned r0 = (mt * 16 + gid) * AS_STRIDE + kc + tig;
            unsigned a[4];
            a[0] = AsU[r0];
            a[1] = AsU[r0 + 8 * AS_STRIDE];
            a[2] = AsU[r0 + 4];
            a[3] = AsU[r0 + 8 * AS_STRIDE + 4];
            mma_tf32(acc[mt][0], a, b0);
            mma_tf32(acc[mt][1], a, b1);
        }
    }

    // ---- epilogue: bias + relu + store (float2, cols adjacent) ----
    #pragma unroll
    for (int nt = 0; nt < 2; nt++) {
        int col = warp * 16 + nt * 8 + tig * 2;
        float bb0 = bias[col], bb1 = bias[col + 1];
        #pragma unroll
        for (int mt = 0; mt < 2; mt++) {
            int row = base + mt * 16 + gid;
            float2 v;
            v.x = fmaxf(acc[mt][nt][0] + bb0, 0.0f);
            v.y = fmaxf(acc[mt][nt][1] + bb1, 0.0f);
            *(float2*)&hout[(size_t)row * CH + col] = v;
            v.x = fmaxf(acc[mt][nt][2] + bb0, 0.0f);
            v.y = fmaxf(acc[mt][nt][3] + bb1, 0.0f);
            *(float2*)&hout[(size_t)(row + 8) * CH + col] = v;
        }
    }
}

// ---------------- launch ----------------
extern "C" void kernel_launch(void* const* d_in, const int* in_sizes, int n_in,
                              void* d_out, int out_size) {
    const float* x   = (const float*)d_in[0];
    const int*   ei  = (const int*)d_in[1];      // [2, E]
    const float* W1l = (const float*)d_in[2];
    const float* W1r = (const float*)d_in[3];
    const float* b1  = (const float*)d_in[4];
    const float* W2l = (const float*)d_in[5];
    const float* W2r = (const float*)d_in[6];
    const float* b2  = (const float*)d_in[7];
    const float* W3l = (const float*)d_in[8];
    const float* W3r = (const float*)d_in[9];
    const float* b3  = (const float*)d_in[10];
    float* out = (float*)d_out;

    const int* src = ei;
    const int* dst = ei + N_EDGES;

    float* h1; float* h2; float* Wt2; float* Wt3;
    cudaGetSymbolAddress((void**)&h1, g_h1);
    cudaGetSymbolAddress((void**)&h2, g_h2);
    cudaGetSymbolAddress((void**)&Wt2, g_Wt2);
    cudaGetSymbolAddress((void**)&Wt3, g_Wt3);

    // weight prep + CSR build
    prep_kernel<<<(128 * 256 + 255) / 256, 256>>>(W2l, W2r, W3l, W3r);
    zero_deg_kernel<<<(N_NODES + 255) / 256, 256>>>();
    hist_kernel<<<(N_EDGES + 255) / 256, 256>>>(dst);
    scan1_kernel<<<NCHUNK, 1024>>>();
    scan2_kernel<<<1, 128>>>();
    scan3_kernel<<<NCHUNK, 1024>>>();
    fill_kernel<<<(N_EDGES + 255) / 256, 256>>>(src, dst);

    // layers
    layer1_kernel<<<(N_NODES + 63) / 64, 128>>>(x, W1l, W1r, b1, h1);
    layerTC_kernel<<<N_NODES / NPB, 256>>>(h1, h2, Wt2, b2);
    layerTC_kernel<<<N_NODES / NPB, 256>>>(h2, out, Wt3, b3);
}

// round 6
// speedup vs baseline: 3.0826x; 1.6881x over previous
#include <cuda_runtime.h>
#include <cstdint>

#define N_NODES 100000
#define N_EDGES 600000
#define CH 128
#define NPB 32            // nodes per block tile (100000 % 32 == 0 -> 3125 blocks)
#define NCHUNK 98         // ceil(100000/1024)

// ---------------- scratch (static device globals; no allocation) ----------------
__device__ int   g_deg[N_NODES];
__device__ float g_deginv[N_NODES];
__device__ int   g_off[N_NODES + 1];
__device__ int   g_cur[N_NODES];
__device__ int   g_col[N_EDGES];
__device__ int   g_chunksum[NCHUNK];
__device__ int   g_chunkoff[NCHUNK];
__device__ float g_h1[(size_t)N_NODES * CH];
__device__ float g_h2[(size_t)N_NODES * CH];
// fragment-ordered weights: pair index = ((warp*32 + kt)*2 + nt)*32 + lane, 2 floats each
__device__ float g_Wt2[128 * 256];
__device__ float g_Wt3[128 * 256];

// ---------------- helpers ----------------
__device__ __forceinline__ float tf32r(float x) {
    unsigned r;
    asm("cvt.rna.tf32.f32 %0, %1;" : "=r"(r) : "f"(x));   // tf32 cvt writes .b32
    return __uint_as_float(r);
}
__device__ __forceinline__ int warp_incl_scan(int v, int lane) {
    #pragma unroll
    for (int o = 1; o < 32; o <<= 1) {
        int t = __shfl_up_sync(0xffffffffu, v, o);
        if (lane >= o) v += t;
    }
    return v;
}
__device__ __forceinline__ void mma_tf32(float* c, const unsigned* a, const unsigned* b) {
    asm volatile(
        "mma.sync.aligned.m16n8k8.row.col.f32.tf32.tf32.f32 "
        "{%0,%1,%2,%3}, {%4,%5,%6,%7}, {%8,%9}, {%0,%1,%2,%3};"
        : "+f"(c[0]), "+f"(c[1]), "+f"(c[2]), "+f"(c[3])
        : "r"(a[0]), "r"(a[1]), "r"(a[2]), "r"(a[3]), "r"(b[0]), "r"(b[1]));
}

// ---------------- weight prep: fragment-order shuffle + concat + tf32 round ----------------
// For pair p: lane=p&31, nt=(p>>5)&1, kt=(p>>6)&31, warp=(p>>11)&7
//   gid=lane>>2, tig=lane&3, n = warp*16 + nt*8 + gid, k = kt*8 + tig
//   value0 = W[n][k], value1 = W[n][k+4]   (k<128 -> Wl[k][n], else Wr[k-128][n])
__global__ void prep_kernel(const float* __restrict__ W2l, const float* __restrict__ W2r,
                            const float* __restrict__ W3l, const float* __restrict__ W3r) {
    int p = blockIdx.x * blockDim.x + threadIdx.x;   // 16384 pairs
    if (p >= 16384) return;
    int lane = p & 31;
    int nt   = (p >> 5) & 1;
    int kt   = (p >> 6) & 31;
    int warp = (p >> 11) & 7;
    int gid = lane >> 2, tig = lane & 3;
    int n  = warp * 16 + nt * 8 + gid;
    int k0 = kt * 8 + tig;
    int k1 = k0 + 4;

    float v2a = (k0 < 128) ? W2l[k0 * CH + n] : W2r[(k0 - 128) * CH + n];
    float v2b = (k1 < 128) ? W2l[k1 * CH + n] : W2r[(k1 - 128) * CH + n];
    float v3a = (k0 < 128) ? W3l[k0 * CH + n] : W3r[(k0 - 128) * CH + n];
    float v3b = (k1 < 128) ? W3l[k1 * CH + n] : W3r[(k1 - 128) * CH + n];
    g_Wt2[p * 2 + 0] = tf32r(v2a);
    g_Wt2[p * 2 + 1] = tf32r(v2b);
    g_Wt3[p * 2 + 0] = tf32r(v3a);
    g_Wt3[p * 2 + 1] = tf32r(v3b);
}

// ---------------- CSR build ----------------
__global__ void zero_deg_kernel() {
    int i = blockIdx.x * blockDim.x + threadIdx.x;
    if (i < N_NODES) g_deg[i] = 0;
}

__global__ void hist_kernel(const int* __restrict__ dst) {
    int i = blockIdx.x * blockDim.x + threadIdx.x;
    if (i < N_EDGES) atomicAdd(&g_deg[dst[i]], 1);
}

// phase 1: per-1024-chunk inclusive scan (parallel over chunks)
__global__ void scan1_kernel() {
    __shared__ int wsum[32];
    int b = blockIdx.x, tid = threadIdx.x;
    int wid = tid >> 5, lane = tid & 31;
    int i = b * 1024 + tid;
    int v = (i < N_NODES) ? g_deg[i] : 0;
    if (i < N_NODES) g_deginv[i] = (v > 0) ? (1.0f / (float)v) : 0.0f;

    int incl = warp_incl_scan(v, lane);
    if (lane == 31) wsum[wid] = incl;
    __syncthreads();
    if (wid == 0) {
        int ws = wsum[lane];
        int wi = warp_incl_scan(ws, lane);
        wsum[lane] = wi - ws;   // exclusive warp prefix
    }
    __syncthreads();
    int inclusive = wsum[wid] + incl;
    if (i < N_NODES) g_off[i + 1] = inclusive;      // chunk-local inclusive
    if (tid == 1023) g_chunksum[b] = inclusive;     // chunk total
}

// phase 2: scan the 98 chunk sums
__global__ void scan2_kernel() {
    __shared__ int ws[4];
    int tid = threadIdx.x, wid = tid >> 5, lane = tid & 31;
    int v = (tid < NCHUNK) ? g_chunksum[tid] : 0;
    int incl = warp_incl_scan(v, lane);
    if (lane == 31) ws[wid] = incl;
    __syncthreads();
    int woff = 0;
    #pragma unroll
    for (int w = 0; w < 4; w++) if (w < wid) woff += ws[w];
    if (tid < NCHUNK) g_chunkoff[tid] = woff + incl - v;   // exclusive chunk offset
}

// phase 3: add chunk offsets back, produce g_off / g_cur
__global__ void scan3_kernel() {
    int b = blockIdx.x, tid = threadIdx.x;
    int i = b * 1024 + tid;
    if (i < N_NODES) {
        int incl = g_off[i + 1] + g_chunkoff[b];
        g_off[i + 1] = incl;
        g_cur[i]     = incl - g_deg[i];
        if (i == 0) g_off[0] = 0;
    }
}

__global__ void fill_kernel(const int* __restrict__ src, const int* __restrict__ dst) {
    int i = blockIdx.x * blockDim.x + threadIdx.x;
    if (i < N_EDGES) {
        int d   = dst[i];
        int pos = atomicAdd(&g_cur[d], 1);
        g_col[pos] = src[i];
    }
}

// ---------------- layer 1 (K = 3, exact fp32) ----------------
__global__ void layer1_kernel(const float* __restrict__ x,
                              const float* __restrict__ Wl,
                              const float* __restrict__ Wr,
                              const float* __restrict__ b,
                              float* __restrict__ hout) {
    __shared__ float aggx[64][4];
    __shared__ float xs[64][4];
    int tid  = threadIdx.x;
    int warp = tid >> 5, lane = tid & 31;
    int base = blockIdx.x * 64;

    for (int n = warp; n < 64; n += 4) {
        int node = base + n;
        if (node >= N_NODES) break;
        int s0 = g_off[node], e0 = g_off[node + 1];
        float a0 = 0.f, a1 = 0.f, a2 = 0.f;
        for (int idx = s0 + lane; idx < e0; idx += 32) {
            int j = g_col[idx];
            a0 += x[j * 3 + 0];
            a1 += x[j * 3 + 1];
            a2 += x[j * 3 + 2];
        }
        #pragma unroll
        for (int o = 16; o > 0; o >>= 1) {
            a0 += __shfl_xor_sync(0xffffffffu, a0, o);
            a1 += __shfl_xor_sync(0xffffffffu, a1, o);
            a2 += __shfl_xor_sync(0xffffffffu, a2, o);
        }
        if (lane == 0) {
            float di = g_deginv[node];
            aggx[n][0] = a0 * di; aggx[n][1] = a1 * di; aggx[n][2] = a2 * di;
            xs[n][0] = x[node * 3 + 0];
            xs[n][1] = x[node * 3 + 1];
            xs[n][2] = x[node * 3 + 2];
        }
    }
    __syncthreads();

    int t = tid;
    float wl0 = Wl[0 * CH + t], wl1 = Wl[1 * CH + t], wl2 = Wl[2 * CH + t];
    float wr0 = Wr[0 * CH + t], wr1 = Wr[1 * CH + t], wr2 = Wr[2 * CH + t];
    float bb  = b[t];
    for (int n = 0; n < 64; n++) {
        int node = base + n;
        if (node >= N_NODES) break;
        float acc = bb;
        acc += aggx[n][0] * wl0 + aggx[n][1] * wl1 + aggx[n][2] * wl2;
        acc += xs[n][0]   * wr0 + xs[n][1]   * wr1 + xs[n][2]   * wr2;
        hout[(size_t)node * CH + t] = fmaxf(acc, 0.0f);
    }
}

// ---------------- layers 2/3: gather-aggregate + tf32 tensor-core GEMM + relu ----------------
// A tile = [agg | own] : 32 nodes x 256 K, vs frag-ordered Wt -> 32x128 out.
#define AS_STRIDE 260
__global__ void __launch_bounds__(256)
layerTC_kernel(const float* __restrict__ hin, float* __restrict__ hout,
               const float* __restrict__ Wt, const float* __restrict__ bias) {
    __shared__ __align__(16) float As[NPB][AS_STRIDE];   // 33,280 B

    int tid  = threadIdx.x;
    int warp = tid >> 5, lane = tid & 31;
    int base = blockIdx.x * NPB;

    // ---- Phase A: mean-aggregate + own row, tf32-rounded, into shared ----
    for (int n = warp; n < NPB; n += 8) {
        int node = base + n;
        float4 own = *(const float4*)&hin[(size_t)node * CH + lane * 4];

        int s0 = g_off[node], e0 = g_off[node + 1];
        float4 A0 = make_float4(0.f, 0.f, 0.f, 0.f);
        float4 A1 = A0, A2 = A0, A3 = A0;
        int idx = s0;
        for (; idx + 4 <= e0; idx += 4) {
            int j0 = g_col[idx + 0], j1 = g_col[idx + 1];
            int j2 = g_col[idx + 2], j3 = g_col[idx + 3];
            float4 v0 = *(const float4*)&hin[(size_t)j0 * CH + lane * 4];
            float4 v1 = *(const float4*)&hin[(size_t)j1 * CH + lane * 4];
            float4 v2 = *(const float4*)&hin[(size_t)j2 * CH + lane * 4];
            float4 v3 = *(const float4*)&hin[(size_t)j3 * CH + lane * 4];
            A0.x += v0.x; A0.y += v0.y; A0.z += v0.z; A0.w += v0.w;
            A1.x += v1.x; A1.y += v1.y; A1.z += v1.z; A1.w += v1.w;
            A2.x += v2.x; A2.y += v2.y; A2.z += v2.z; A2.w += v2.w;
            A3.x += v3.x; A3.y += v3.y; A3.z += v3.z; A3.w += v3.w;
        }
        for (; idx < e0; idx++) {
            int j = g_col[idx];
            float4 v = *(const float4*)&hin[(size_t)j * CH + lane * 4];
            A0.x += v.x; A0.y += v.y; A0.z += v.z; A0.w += v.w;
        }
        float di = g_deginv[node];
        As[n][lane * 4 + 0] = tf32r(((A0.x + A1.x) + (A2.x + A3.x)) * di);
        As[n][lane * 4 + 1] = tf32r(((A0.y + A1.y) + (A2.y + A3.y)) * di);
        As[n][lane * 4 + 2] = tf32r(((A0.z + A1.z) + (A2.z + A3.z)) * di);
        As[n][lane * 4 + 3] = tf32r(((A0.w + A1.w) + (A2.w + A3.w)) * di);
        As[n][128 + lane * 4 + 0] = tf32r(own.x);
        As[n][128 + lane * 4 + 1] = tf32r(own.y);
        As[n][128 + lane * 4 + 2] = tf32r(own.z);
        As[n][128 + lane * 4 + 3] = tf32r(own.w);
    }
    __syncthreads();

    // ---- Phase B: 32x128 = (32x256) @ (256x128) via m16n8k8 tf32 mma ----
    // B fragments are pre-shuffled into per-lane order: 2 coalesced LDG.64 per kt.
    int gid = lane >> 2, tig = lane & 3;
    float acc[2][2][4];
    #pragma unroll
    for (int mt = 0; mt < 2; mt++)
        #pragma unroll
        for (int nt = 0; nt < 2; nt++)
            #pragma unroll
            for (int r = 0; r < 4; r++) acc[mt][nt][r] = 0.0f;

    const float2* Wf = (const float2*)Wt;
    const unsigned* AsU = (const unsigned*)&As[0][0];

    #pragma unroll 4
    for (int kt = 0; kt < 32; kt++) {
        unsigned i0 = ((unsigned)(warp * 32 + kt) * 2) * 32 + lane;
        float2 f0 = Wf[i0];        // nt = 0
        float2 f1 = Wf[i0 + 32];   // nt = 1
        unsigned b0[2] = { __float_as_uint(f0.x), __float_as_uint(f0.y) };
        unsigned b1[2] = { __float_as_uint(f1.x), __float_as_uint(f1.y) };

        unsigned kc = kt * 8;
        #pragma unroll
        for (int mt = 0; mt < 2; mt++) {
            unsigned r0 = (mt * 16 + gid) * AS_STRIDE + kc + tig;
            unsigned a[4];
            a[0] = AsU[r0];
            a[1] = AsU[r0 + 8 * AS_STRIDE];
            a[2] = AsU[r0 + 4];
            a[3] = AsU[r0 + 8 * AS_STRIDE + 4];
            mma_tf32(acc[mt][0], a, b0);
            mma_tf32(acc[mt][1], a, b1);
        }
    }

    // ---- epilogue: bias + relu + store (float2, cols adjacent) ----
    #pragma unroll
    for (int nt = 0; nt < 2; nt++) {
        int col = warp * 16 + nt * 8 + tig * 2;
        float bb0 = bias[col], bb1 = bias[col + 1];
        #pragma unroll
        for (int mt = 0; mt < 2; mt++) {
            int row = base + mt * 16 + gid;
            float2 v;
            v.x = fmaxf(acc[mt][nt][0] + bb0, 0.0f);
            v.y = fmaxf(acc[mt][nt][1] + bb1, 0.0f);
            *(float2*)&hout[(size_t)row * CH + col] = v;
            v.x = fmaxf(acc[mt][nt][2] + bb0, 0.0f);
            v.y = fmaxf(acc[mt][nt][3] + bb1, 0.0f);
            *(float2*)&hout[(size_t)(row + 8) * CH + col] = v;
        }
    }
}

// ---------------- launch ----------------
extern "C" void kernel_launch(void* const* d_in, const int* in_sizes, int n_in,
                              void* d_out, int out_size) {
    const float* x   = (const float*)d_in[0];
    const int*   ei  = (const int*)d_in[1];      // [2, E]
    const float* W1l = (const float*)d_in[2];
    const float* W1r = (const float*)d_in[3];
    const float* b1  = (const float*)d_in[4];
    const float* W2l = (const float*)d_in[5];
    const float* W2r = (const float*)d_in[6];
    const float* b2  = (const float*)d_in[7];
    const float* W3l = (const float*)d_in[8];
    const float* W3r = (const float*)d_in[9];
    const float* b3  = (const float*)d_in[10];
    float* out = (float*)d_out;

    const int* src = ei;
    const int* dst = ei + N_EDGES;

    float* h1; float* h2; float* Wt2; float* Wt3;
    cudaGetSymbolAddress((void**)&h1, g_h1);
    cudaGetSymbolAddress((void**)&h2, g_h2);
    cudaGetSymbolAddress((void**)&Wt2, g_Wt2);
    cudaGetSymbolAddress((void**)&Wt3, g_Wt3);

    // weight prep + CSR build
    prep_kernel<<<(16384 + 255) / 256, 256>>>(W2l, W2r, W3l, W3r);
    zero_deg_kernel<<<(N_NODES + 255) / 256, 256>>>();
    hist_kernel<<<(N_EDGES + 255) / 256, 256>>>(dst);
    scan1_kernel<<<NCHUNK, 1024>>>();
    scan2_kernel<<<1, 128>>>();
    scan3_kernel<<<NCHUNK, 1024>>>();
    fill_kernel<<<(N_EDGES + 255) / 256, 256>>>(src, dst);

    // layers
    layer1_kernel<<<(N_NODES + 63) / 64, 128>>>(x, W1l, W1r, b1, h1);
    layerTC_kernel<<<N_NODES / NPB, 256>>>(h1, h2, Wt2, b2);
    layerTC_kernel<<<N_NODES / NPB, 256>>>(h2, out, Wt3, b3);
}